// round 2
// baseline (speedup 1.0000x reference)
#include <cuda_runtime.h>
#include <math.h>

// Problem constants
#define Bn   4
#define Sn   4096
#define Dn   1024
#define Mn   128
#define Cn   128          // chunk length
#define NCn  (Sn / Cn)    // 32 chunks
#define BSn  (Bn * Sn)    // 16384 rows
#define DECAYF 0.99f
#define LRF    0.01f

// Scratch (device globals; no allocations allowed)
__device__ float g_k  [BSn * Mn];
__device__ float g_v  [BSn * Mn];
__device__ float g_q  [BSn * Mn];
__device__ float g_att[BSn * Mn];
__device__ float g_dS [Bn * NCn * Mn * Mn];   // per-chunk state increment (decayed to chunk end)
__device__ float g_S  [Bn * NCn * Mn * Mn];   // state BEFORE each chunk

#define LOAD8(dst, ptr) do { \
    float4 _t0 = *(const float4*)(ptr); \
    float4 _t1 = *(const float4*)((ptr) + 4); \
    (dst)[0]=_t0.x; (dst)[1]=_t0.y; (dst)[2]=_t0.z; (dst)[3]=_t0.w; \
    (dst)[4]=_t1.x; (dst)[5]=_t1.y; (dst)[6]=_t1.z; (dst)[7]=_t1.w; \
} while (0)

// ---------------------------------------------------------------------------
// Generic SGEMM body: C[128, 128-tile] = A[128, Kg] * W^T  (+ bias)
// A row-major [*,Kg] (lda), W row-major [128 rows of this tile, Kg] (ldw).
// 256 threads, 8x8 microtile per thread, BK=8.
// ---------------------------------------------------------------------------
__device__ __forceinline__ void sgemm128_tn(
    const float* __restrict__ A, int lda,
    const float* __restrict__ W, int ldw,
    const float* __restrict__ bias,
    float* __restrict__ C, int ldc, int Kg)
{
    __shared__ float As[8][128];
    __shared__ float Bs[8][128];
    const int tid  = threadIdx.x;
    const int lrow = tid >> 1;          // 0..127
    const int lk   = (tid & 1) << 2;    // 0 or 4
    const int ty   = tid >> 4;          // 0..15
    const int tx   = tid & 15;          // 0..15

    float acc[8][8];
#pragma unroll
    for (int i = 0; i < 8; i++)
#pragma unroll
        for (int j = 0; j < 8; j++) acc[i][j] = 0.f;

    for (int k0 = 0; k0 < Kg; k0 += 8) {
        float4 av = *(const float4*)(A + (size_t)lrow * lda + k0 + lk);
        float4 wv = *(const float4*)(W + (size_t)lrow * ldw + k0 + lk);
        __syncthreads();
        As[lk+0][lrow]=av.x; As[lk+1][lrow]=av.y; As[lk+2][lrow]=av.z; As[lk+3][lrow]=av.w;
        Bs[lk+0][lrow]=wv.x; Bs[lk+1][lrow]=wv.y; Bs[lk+2][lrow]=wv.z; Bs[lk+3][lrow]=wv.w;
        __syncthreads();
#pragma unroll
        for (int kk = 0; kk < 8; kk++) {
            float ar[8], br[8];
            LOAD8(ar, &As[kk][ty * 8]);
            LOAD8(br, &Bs[kk][tx * 8]);
#pragma unroll
            for (int i = 0; i < 8; i++)
#pragma unroll
                for (int j = 0; j < 8; j++)
                    acc[i][j] = fmaf(ar[i], br[j], acc[i][j]);
        }
    }

    float bregs[8];
#pragma unroll
    for (int j = 0; j < 8; j++) bregs[j] = bias ? bias[tx * 8 + j] : 0.f;

#pragma unroll
    for (int i = 0; i < 8; i++) {
        int r = ty * 8 + i;
        float4 o0, o1;
        o0.x = acc[i][0] + bregs[0]; o0.y = acc[i][1] + bregs[1];
        o0.z = acc[i][2] + bregs[2]; o0.w = acc[i][3] + bregs[3];
        o1.x = acc[i][4] + bregs[4]; o1.y = acc[i][5] + bregs[5];
        o1.z = acc[i][6] + bregs[6]; o1.w = acc[i][7] + bregs[7];
        *(float4*)(C + (size_t)r * ldc + tx * 8)     = o0;
        *(float4*)(C + (size_t)r * ldc + tx * 8 + 4) = o1;
    }
}

// ---------------------------------------------------------------------------
// K1: projections k/v/q = x @ W^T + b   grid (BS/128, 3)
// ---------------------------------------------------------------------------
__global__ void __launch_bounds__(256) proj_kernel(
    const float* __restrict__ x,
    const float* __restrict__ Wk, const float* __restrict__ bk,
    const float* __restrict__ Wv, const float* __restrict__ bv,
    const float* __restrict__ Wq, const float* __restrict__ bq)
{
    const int rb = blockIdx.x * 128;
    const float* W; const float* bias; float* outp;
    if (blockIdx.y == 0)      { W = Wk; bias = bk; outp = g_k; }
    else if (blockIdx.y == 1) { W = Wv; bias = bv; outp = g_v; }
    else                      { W = Wq; bias = bq; outp = g_q; }
    sgemm128_tn(x + (size_t)rb * Dn, Dn, W, Dn, bias, outp + (size_t)rb * Mn, Mn, Dn);
}

// ---------------------------------------------------------------------------
// K5: y = att @ Wo^T + bo   grid (BS/128, D/128)
// ---------------------------------------------------------------------------
__global__ void __launch_bounds__(256) outproj_kernel(
    const float* __restrict__ Wo, const float* __restrict__ bo, float* __restrict__ y)
{
    const int rb = blockIdx.x * 128;
    const int cb = blockIdx.y * 128;
    sgemm128_tn(g_att + (size_t)rb * Mn, Mn, Wo + (size_t)cb * Mn, Mn,
                bo + cb, y + (size_t)rb * Dn + cb, Dn, Mn);
}

// ---------------------------------------------------------------------------
// K2: per (b,c): A^T[u][t] = q_t·k_u (u<t, *lr*decay^(t-1-u)),
//     out_intra = A @ V, dS = sum_u lr*decay^(C-1-u) v_u k_u^T
// grid = B*NC blocks, 256 threads, 197120 B dynamic smem
// ---------------------------------------------------------------------------
extern __shared__ float sm_dyn[];
__global__ void __launch_bounds__(256) chunk_kernel()
{
    float* B0   = sm_dyn;            // sKt [d][u]
    float* B1   = B0 + 16384;        // sQt [d][t] -> sAt [u][t] -> sK natural [u][j]
    float* B2   = B1 + 16384;        // sV  [u][i]
    float* dpow = B2 + 16384;        // decay^0..127

    const int tid = threadIdx.x;
    const int b = blockIdx.x / NCn;
    const int c = blockIdx.x % NCn;
    const size_t base = ((size_t)b * Sn + (size_t)c * Cn) * Mn;

    // Load K,Q transposed ([d][u]) and V natural ([u][i])
    for (int idx = tid * 4; idx < Cn * Mn; idx += 1024) {
        const int u = idx >> 7, d = idx & 127;
        float4 kv = *(const float4*)(g_k + base + idx);
        float4 qv = *(const float4*)(g_q + base + idx);
        B0[(d+0)*128+u]=kv.x; B0[(d+1)*128+u]=kv.y; B0[(d+2)*128+u]=kv.z; B0[(d+3)*128+u]=kv.w;
        B1[(d+0)*128+u]=qv.x; B1[(d+1)*128+u]=qv.y; B1[(d+2)*128+u]=qv.z; B1[(d+3)*128+u]=qv.w;
        *(float4*)(B2 + idx) = *(const float4*)(g_v + base + idx);
    }
    if (tid < 128) dpow[tid] = powf(DECAYF, (float)tid);
    __syncthreads();

    const int ty = tid >> 4, tx = tid & 15;

    // GEMM1: At[u][t] = sum_d k_u[d]*q_t[d]; rows u=ty*8+i, cols t=tx*8+j
    float acc[8][8];
#pragma unroll
    for (int i = 0; i < 8; i++)
#pragma unroll
        for (int j = 0; j < 8; j++) acc[i][j] = 0.f;
    for (int d = 0; d < 128; d++) {
        float kr[8], qr[8];
        LOAD8(kr, &B0[d * 128 + ty * 8]);
        LOAD8(qr, &B1[d * 128 + tx * 8]);
#pragma unroll
        for (int i = 0; i < 8; i++)
#pragma unroll
            for (int j = 0; j < 8; j++)
                acc[i][j] = fmaf(kr[i], qr[j], acc[i][j]);
    }
    // mask (strict: u < t, readout uses pre-update state) + decay*lr
#pragma unroll
    for (int i = 0; i < 8; i++)
#pragma unroll
        for (int j = 0; j < 8; j++) {
            const int u = ty * 8 + i, t = tx * 8 + j;
            acc[i][j] = (u < t) ? acc[i][j] * (LRF * dpow[t - 1 - u]) : 0.f;
        }
    __syncthreads();   // everyone done reading Q before overwrite
    // store At into B1: row u, cols t (conflict-free float4 row stores)
#pragma unroll
    for (int i = 0; i < 8; i++) {
        const int u = ty * 8 + i;
        float4 o0 = make_float4(acc[i][0], acc[i][1], acc[i][2], acc[i][3]);
        float4 o1 = make_float4(acc[i][4], acc[i][5], acc[i][6], acc[i][7]);
        *(float4*)(B1 + u * 128 + tx * 8)     = o0;
        *(float4*)(B1 + u * 128 + tx * 8 + 4) = o1;
    }
    __syncthreads();

    // GEMM2: out_intra[t][i] = sum_u At[u][t]*V[u][i]; rows t=ty*8+i, cols i=tx*8+j
    float acc2[8][8];
#pragma unroll
    for (int i = 0; i < 8; i++)
#pragma unroll
        for (int j = 0; j < 8; j++) acc2[i][j] = 0.f;
    for (int u = 0; u < 128; u++) {
        float ar[8], vr[8];
        LOAD8(ar, &B1[u * 128 + ty * 8]);
        LOAD8(vr, &B2[u * 128 + tx * 8]);
#pragma unroll
        for (int i = 0; i < 8; i++)
#pragma unroll
            for (int j = 0; j < 8; j++)
                acc2[i][j] = fmaf(ar[i], vr[j], acc2[i][j]);
    }
#pragma unroll
    for (int i = 0; i < 8; i++) {
        const int t = ty * 8 + i;
        float4 o0 = make_float4(acc2[i][0], acc2[i][1], acc2[i][2], acc2[i][3]);
        float4 o1 = make_float4(acc2[i][4], acc2[i][5], acc2[i][6], acc2[i][7]);
        *(float4*)(g_att + base + (size_t)t * 128 + tx * 8)     = o0;
        *(float4*)(g_att + base + (size_t)t * 128 + tx * 8 + 4) = o1;
    }
    __syncthreads();

    // reload K natural [u][j] into B1 (coalesced; avoids smem transpose conflicts)
    for (int idx = tid * 4; idx < Cn * Mn; idx += 1024)
        *(float4*)(B1 + idx) = *(const float4*)(g_k + base + idx);
    __syncthreads();

    // GEMM3: dS[i][j] = sum_u (lr*decay^(127-u)) * v_u[i] * k_u[j]
    float acc3[8][8];
#pragma unroll
    for (int i = 0; i < 8; i++)
#pragma unroll
        for (int j = 0; j < 8; j++) acc3[i][j] = 0.f;
    for (int u = 0; u < 128; u++) {
        const float w = LRF * dpow[127 - u];
        float vr[8], kr[8];
        LOAD8(vr, &B2[u * 128 + ty * 8]);
        LOAD8(kr, &B1[u * 128 + tx * 8]);
        float vw[8];
#pragma unroll
        for (int i = 0; i < 8; i++) vw[i] = vr[i] * w;
#pragma unroll
        for (int i = 0; i < 8; i++)
#pragma unroll
            for (int j = 0; j < 8; j++)
                acc3[i][j] = fmaf(vw[i], kr[j], acc3[i][j]);
    }
    const size_t dsbase = ((size_t)b * NCn + c) * (Mn * Mn);
#pragma unroll
    for (int i = 0; i < 8; i++) {
        const int r = ty * 8 + i;
        float4 o0 = make_float4(acc3[i][0], acc3[i][1], acc3[i][2], acc3[i][3]);
        float4 o1 = make_float4(acc3[i][4], acc3[i][5], acc3[i][6], acc3[i][7]);
        *(float4*)(g_dS + dsbase + (size_t)r * 128 + tx * 8)     = o0;
        *(float4*)(g_dS + dsbase + (size_t)r * 128 + tx * 8 + 4) = o1;
    }
}

// ---------------------------------------------------------------------------
// K3: sequential prefix over chunks (32 steps, elementwise). Also emits final state.
// ---------------------------------------------------------------------------
__global__ void __launch_bounds__(256) scan_kernel(float* __restrict__ state_out)
{
    const int g  = blockIdx.x * blockDim.x + threadIdx.x;  // 0..65535
    const int b  = g >> 14;
    const int ij = g & 16383;
    const float dc = powf(DECAYF, (float)Cn);
    float s = 0.f;
    for (int c = 0; c < NCn; c++) {
        const size_t idx = ((size_t)b * NCn + c) * 16384 + ij;
        g_S[idx] = s;                 // state BEFORE chunk c
        s = dc * s + g_dS[idx];
    }
    state_out[g] = s;                 // final state output
}

// ---------------------------------------------------------------------------
// K4: out[t][i] += decay^tl * sum_j S_c[i][j]*q_t[j]
// grid = B*NC blocks, 256 threads, 131584 B dynamic smem
// ---------------------------------------------------------------------------
__global__ void __launch_bounds__(256) inter_kernel()
{
    float* sQt  = sm_dyn;           // [j][t]
    float* sSt  = sQt + 16384;      // [j][i]  (S transposed)
    float* dpow = sSt + 16384;

    const int tid = threadIdx.x;
    const int b = blockIdx.x / NCn;
    const int c = blockIdx.x % NCn;
    const size_t base  = ((size_t)b * Sn + (size_t)c * Cn) * Mn;
    const size_t sbase = ((size_t)b * NCn + c) * 16384;

    for (int idx = tid * 4; idx < 16384; idx += 1024) {
        const int r = idx >> 7, d = idx & 127;    // q: (t=r, j=d);  S: (i=r, j=d)
        float4 qv = *(const float4*)(g_q + base + idx);
        float4 sv = *(const float4*)(g_S + sbase + idx);
        sQt[(d+0)*128+r]=qv.x; sQt[(d+1)*128+r]=qv.y; sQt[(d+2)*128+r]=qv.z; sQt[(d+3)*128+r]=qv.w;
        sSt[(d+0)*128+r]=sv.x; sSt[(d+1)*128+r]=sv.y; sSt[(d+2)*128+r]=sv.z; sSt[(d+3)*128+r]=sv.w;
    }
    if (tid < 128) dpow[tid] = powf(DECAYF, (float)tid);
    __syncthreads();

    const int ty = tid >> 4, tx = tid & 15;
    float acc[8][8];
#pragma unroll
    for (int i = 0; i < 8; i++)
#pragma unroll
        for (int j = 0; j < 8; j++) acc[i][j] = 0.f;
    for (int j = 0; j < 128; j++) {
        float qr[8], sr[8];
        LOAD8(qr, &sQt[j * 128 + ty * 8]);
        LOAD8(sr, &sSt[j * 128 + tx * 8]);
#pragma unroll
        for (int i = 0; i < 8; i++)
#pragma unroll
            for (int jj = 0; jj < 8; jj++)
                acc[i][jj] = fmaf(qr[i], sr[jj], acc[i][jj]);
    }
#pragma unroll
    for (int i = 0; i < 8; i++) {
        const int t = ty * 8 + i;
        const float f = dpow[t];
        float4* p0 = (float4*)(g_att + base + (size_t)t * 128 + tx * 8);
        float4* p1 = p0 + 1;
        float4 a0 = *p0, a1 = *p1;
        a0.x += f * acc[i][0]; a0.y += f * acc[i][1]; a0.z += f * acc[i][2]; a0.w += f * acc[i][3];
        a1.x += f * acc[i][4]; a1.y += f * acc[i][5]; a1.z += f * acc[i][6]; a1.w += f * acc[i][7];
        *p0 = a0; *p1 = a1;
    }
}

// ---------------------------------------------------------------------------
extern "C" void kernel_launch(void* const* d_in, const int* in_sizes, int n_in,
                              void* d_out, int out_size)
{
    const float* x  = (const float*)d_in[0];
    const float* Wk = (const float*)d_in[1];
    const float* bk = (const float*)d_in[2];
    const float* Wv = (const float*)d_in[3];
    const float* bv = (const float*)d_in[4];
    const float* Wq = (const float*)d_in[5];
    const float* bq = (const float*)d_in[6];
    const float* Wo = (const float*)d_in[7];
    const float* bo = (const float*)d_in[8];

    float* y         = (float*)d_out;
    float* state_out = y + (size_t)BSn * Dn;

    cudaFuncSetAttribute(chunk_kernel, cudaFuncAttributeMaxDynamicSharedMemorySize, 197120);
    cudaFuncSetAttribute(inter_kernel, cudaFuncAttributeMaxDynamicSharedMemorySize, 131584);

    proj_kernel<<<dim3(BSn / 128, 3), 256>>>(x, Wk, bk, Wv, bv, Wq, bq);
    chunk_kernel<<<Bn * NCn, 256, 197120>>>();
    scan_kernel<<<(Bn * Mn * Mn) / 256, 256>>>(state_out);
    inter_kernel<<<Bn * NCn, 256, 131584>>>();
    outproj_kernel<<<dim3(BSn / 128, Dn / 128), 256>>>(Wo, bo, y);
}

// round 4
// speedup vs baseline: 1.4834x; 1.4834x over previous
#include <cuda_runtime.h>
#include <math.h>
#include <stdint.h>

// Problem constants
#define Bn   4
#define Sn   4096
#define Dn   1024
#define Mn   128
#define Cn   128          // chunk length
#define NCn  (Sn / Cn)    // 32 chunks
#define BSn  (Bn * Sn)    // 16384 rows
#define DECAYF 0.99f
#define LRF    0.01f

// Scratch (device globals; no allocations allowed)
__device__ float g_k  [BSn * Mn];
__device__ float g_v  [BSn * Mn];
__device__ float g_q  [BSn * Mn];
__device__ float g_att[BSn * Mn];
__device__ float g_dS [Bn * NCn * Mn * Mn];
__device__ float g_S  [Bn * NCn * Mn * Mn];

#define LOAD8(dst, ptr) do { \
    float4 _t0 = *(const float4*)(ptr); \
    float4 _t1 = *(const float4*)((ptr) + 4); \
    (dst)[0]=_t0.x; (dst)[1]=_t0.y; (dst)[2]=_t0.z; (dst)[3]=_t0.w; \
    (dst)[4]=_t1.x; (dst)[5]=_t1.y; (dst)[6]=_t1.z; (dst)[7]=_t1.w; \
} while (0)

// ===========================================================================
// tf32 mma.sync helpers (sm_80+ PTX — no sm_103a-only features)
// ===========================================================================
__device__ __forceinline__ float to_tf32(float x) {
    float y;
    asm("cvt.rna.tf32.f32 %0, %1;" : "=f"(y) : "f"(x));
    return y;
}

__device__ __forceinline__ void mma_16n8k8(float* d, const uint32_t* a, const uint32_t* b) {
    asm volatile(
        "mma.sync.aligned.m16n8k8.row.col.f32.tf32.tf32.f32 "
        "{%0,%1,%2,%3}, {%4,%5,%6,%7}, {%8,%9}, {%0,%1,%2,%3};"
        : "+f"(d[0]), "+f"(d[1]), "+f"(d[2]), "+f"(d[3])
        : "r"(a[0]), "r"(a[1]), "r"(a[2]), "r"(a[3]), "r"(b[0]), "r"(b[1]));
}

#define SMLD 20   // padded smem row stride in floats (conflict-free frag loads)

// C[128,128] = A[128,K] * Bm^T (+bias) where Bm is [128 rows, K] row-major.
// 256 threads, 8 warps (4x2), warp tile 32x64, double-buffered K-chunks of 16.
template<bool ACCUM, bool ROWSCALE>
__device__ __forceinline__ void gemm_tn_tf32(
    const float* __restrict__ A, int lda,
    const float* __restrict__ Bm, int ldb, int K,
    const float* __restrict__ bias,
    float* __restrict__ C, int ldc)
{
    __shared__ float sA[2][128 * SMLD];
    __shared__ float sB[2][128 * SMLD];
    const int tid  = threadIdx.x;
    const int lane = tid & 31, wid = tid >> 5;
    const int wm = wid >> 1, wn = wid & 1;
    const int g  = lane >> 2, t4 = lane & 3;

    float acc[2][8][4];
#pragma unroll
    for (int mt = 0; mt < 2; mt++)
#pragma unroll
        for (int nt = 0; nt < 8; nt++)
#pragma unroll
            for (int r = 0; r < 4; r++) acc[mt][nt][r] = 0.f;

    // staging role: each thread owns 8 consecutive floats of one row
    const int srow = tid >> 1;
    const int coff = (tid & 1) * 8;

    float4 pa0, pa1, pb0, pb1;
    {
        const float* ap = A  + (size_t)srow * lda + coff;
        const float* bp = Bm + (size_t)srow * ldb + coff;
        pa0 = *(const float4*)ap; pa1 = *(const float4*)(ap + 4);
        pb0 = *(const float4*)bp; pb1 = *(const float4*)(bp + 4);
    }

    const int nc = K >> 4;
    for (int ch = 0; ch < nc; ch++) {
        const int s = ch & 1;
        {
            float* da = &sA[s][srow * SMLD + coff];
            float* db = &sB[s][srow * SMLD + coff];
            da[0]=to_tf32(pa0.x); da[1]=to_tf32(pa0.y); da[2]=to_tf32(pa0.z); da[3]=to_tf32(pa0.w);
            da[4]=to_tf32(pa1.x); da[5]=to_tf32(pa1.y); da[6]=to_tf32(pa1.z); da[7]=to_tf32(pa1.w);
            db[0]=to_tf32(pb0.x); db[1]=to_tf32(pb0.y); db[2]=to_tf32(pb0.z); db[3]=to_tf32(pb0.w);
            db[4]=to_tf32(pb1.x); db[5]=to_tf32(pb1.y); db[6]=to_tf32(pb1.z); db[7]=to_tf32(pb1.w);
        }
        __syncthreads();
        if (ch + 1 < nc) {
            const int k0 = (ch + 1) * 16;
            const float* ap = A  + (size_t)srow * lda + k0 + coff;
            const float* bp = Bm + (size_t)srow * ldb + k0 + coff;
            pa0 = *(const float4*)ap; pa1 = *(const float4*)(ap + 4);
            pb0 = *(const float4*)bp; pb1 = *(const float4*)(bp + 4);
        }
#pragma unroll
        for (int ks = 0; ks < 2; ks++) {
            const int ko = ks * 8;
            uint32_t af[2][4], bf[8][2];
#pragma unroll
            for (int mt = 0; mt < 2; mt++) {
                const int br = wm * 32 + mt * 16;
                af[mt][0] = __float_as_uint(sA[s][(br + g    ) * SMLD + ko + t4    ]);
                af[mt][1] = __float_as_uint(sA[s][(br + g + 8) * SMLD + ko + t4    ]);
                af[mt][2] = __float_as_uint(sA[s][(br + g    ) * SMLD + ko + t4 + 4]);
                af[mt][3] = __float_as_uint(sA[s][(br + g + 8) * SMLD + ko + t4 + 4]);
            }
#pragma unroll
            for (int nt = 0; nt < 8; nt++) {
                const int bn = wn * 64 + nt * 8 + g;
                bf[nt][0] = __float_as_uint(sB[s][bn * SMLD + ko + t4    ]);
                bf[nt][1] = __float_as_uint(sB[s][bn * SMLD + ko + t4 + 4]);
            }
#pragma unroll
            for (int mt = 0; mt < 2; mt++)
#pragma unroll
                for (int nt = 0; nt < 8; nt++)
                    mma_16n8k8(acc[mt][nt], af[mt], bf[nt]);
        }
        __syncthreads();
    }

    // Epilogue: each thread writes float2 pairs at rows r0, r0+8
#pragma unroll
    for (int mt = 0; mt < 2; mt++) {
        const int r0 = wm * 32 + mt * 16 + g;
#pragma unroll
        for (int nt = 0; nt < 8; nt++) {
            const int c0 = wn * 64 + nt * 8 + 2 * t4;
            float b0 = 0.f, b1 = 0.f;
            if (bias) { b0 = bias[c0]; b1 = bias[c0 + 1]; }
            float* p0 = C + (size_t)r0 * ldc + c0;
            float* p1 = C + (size_t)(r0 + 8) * ldc + c0;
            if (ACCUM) {
                float s0 = 1.f, s1 = 1.f;
                if (ROWSCALE) { s0 = powf(DECAYF, (float)r0); s1 = powf(DECAYF, (float)(r0 + 8)); }
                float2 o0 = *(float2*)p0, o1 = *(float2*)p1;
                o0.x += s0 * acc[mt][nt][0]; o0.y += s0 * acc[mt][nt][1];
                o1.x += s1 * acc[mt][nt][2]; o1.y += s1 * acc[mt][nt][3];
                *(float2*)p0 = o0; *(float2*)p1 = o1;
            } else {
                float2 o0, o1;
                o0.x = acc[mt][nt][0] + b0; o0.y = acc[mt][nt][1] + b1;
                o1.x = acc[mt][nt][2] + b0; o1.y = acc[mt][nt][3] + b1;
                *(float2*)p0 = o0; *(float2*)p1 = o1;
            }
        }
    }
}

// ===========================================================================
// K1: projections k/v/q = x @ W^T + b   grid (128, 3)
// ===========================================================================
__global__ void __launch_bounds__(256) proj_mma_kernel(
    const float* __restrict__ x,
    const float* __restrict__ Wk, const float* __restrict__ bk,
    const float* __restrict__ Wv, const float* __restrict__ bv,
    const float* __restrict__ Wq, const float* __restrict__ bq)
{
    const size_t rb = (size_t)blockIdx.x * 128;
    const float* W; const float* bias; float* outp;
    if (blockIdx.y == 0)      { W = Wk; bias = bk; outp = g_k; }
    else if (blockIdx.y == 1) { W = Wv; bias = bv; outp = g_v; }
    else                      { W = Wq; bias = bq; outp = g_q; }
    gemm_tn_tf32<false, false>(x + rb * Dn, Dn, W, Dn, Dn, bias, outp + rb * Mn, Mn);
}

// ===========================================================================
// K5: y = att @ Wo^T + bo   grid (128, 8)
// ===========================================================================
__global__ void __launch_bounds__(256) outproj_mma_kernel(
    const float* __restrict__ Wo, const float* __restrict__ bo, float* __restrict__ y)
{
    const size_t rb = (size_t)blockIdx.x * 128;
    const int    cb = blockIdx.y * 128;
    gemm_tn_tf32<false, false>(g_att + rb * Mn, Mn, Wo + (size_t)cb * Mn, Mn, Mn,
                               bo + cb, y + rb * Dn + cb, Dn);
}

// ===========================================================================
// K4: out[t][i] += decay^t * sum_j S_c[i][j]*q_t[j]   grid (128)
// ===========================================================================
__global__ void __launch_bounds__(256) inter_mma_kernel()
{
    const int b = blockIdx.x / NCn;
    const int c = blockIdx.x % NCn;
    const size_t base  = ((size_t)b * Sn + (size_t)c * Cn) * Mn;
    const size_t sbase = ((size_t)b * NCn + c) * 16384;
    gemm_tn_tf32<true, true>(g_q + base, Mn, g_S + sbase, Mn, Mn,
                             (const float*)nullptr, g_att + base, Mn);
}

// ===========================================================================
// K2: per (b,c): intra-chunk attention + chunk state increment (SIMT, fp32)
// ===========================================================================
extern __shared__ float sm_dyn[];
__global__ void __launch_bounds__(256) chunk_kernel()
{
    float* B0   = sm_dyn;            // sKt [d][u]
    float* B1   = B0 + 16384;        // sQt [d][t] -> sAt [u][t] -> sK natural
    float* B2   = B1 + 16384;        // sV  [u][i]
    float* dpow = B2 + 16384;

    const int tid = threadIdx.x;
    const int b = blockIdx.x / NCn;
    const int c = blockIdx.x % NCn;
    const size_t base = ((size_t)b * Sn + (size_t)c * Cn) * Mn;

    for (int idx = tid * 4; idx < Cn * Mn; idx += 1024) {
        const int u = idx >> 7, d = idx & 127;
        float4 kv = *(const float4*)(g_k + base + idx);
        float4 qv = *(const float4*)(g_q + base + idx);
        B0[(d+0)*128+u]=kv.x; B0[(d+1)*128+u]=kv.y; B0[(d+2)*128+u]=kv.z; B0[(d+3)*128+u]=kv.w;
        B1[(d+0)*128+u]=qv.x; B1[(d+1)*128+u]=qv.y; B1[(d+2)*128+u]=qv.z; B1[(d+3)*128+u]=qv.w;
        *(float4*)(B2 + idx) = *(const float4*)(g_v + base + idx);
    }
    if (tid < 128) dpow[tid] = powf(DECAYF, (float)tid);
    __syncthreads();

    const int ty = tid >> 4, tx = tid & 15;

    float acc[8][8];
#pragma unroll
    for (int i = 0; i < 8; i++)
#pragma unroll
        for (int j = 0; j < 8; j++) acc[i][j] = 0.f;
    for (int d = 0; d < 128; d++) {
        float kr[8], qr[8];
        LOAD8(kr, &B0[d * 128 + ty * 8]);
        LOAD8(qr, &B1[d * 128 + tx * 8]);
#pragma unroll
        for (int i = 0; i < 8; i++)
#pragma unroll
            for (int j = 0; j < 8; j++)
                acc[i][j] = fmaf(kr[i], qr[j], acc[i][j]);
    }
#pragma unroll
    for (int i = 0; i < 8; i++)
#pragma unroll
        for (int j = 0; j < 8; j++) {
            const int u = ty * 8 + i, t = tx * 8 + j;
            acc[i][j] = (u < t) ? acc[i][j] * (LRF * dpow[t - 1 - u]) : 0.f;
        }
    __syncthreads();
#pragma unroll
    for (int i = 0; i < 8; i++) {
        const int u = ty * 8 + i;
        *(float4*)(B1 + u * 128 + tx * 8)     = make_float4(acc[i][0], acc[i][1], acc[i][2], acc[i][3]);
        *(float4*)(B1 + u * 128 + tx * 8 + 4) = make_float4(acc[i][4], acc[i][5], acc[i][6], acc[i][7]);
    }
    __syncthreads();

    float acc2[8][8];
#pragma unroll
    for (int i = 0; i < 8; i++)
#pragma unroll
        for (int j = 0; j < 8; j++) acc2[i][j] = 0.f;
    for (int u = 0; u < 128; u++) {
        float ar[8], vr[8];
        LOAD8(ar, &B1[u * 128 + ty * 8]);
        LOAD8(vr, &B2[u * 128 + tx * 8]);
#pragma unroll
        for (int i = 0; i < 8; i++)
#pragma unroll
            for (int j = 0; j < 8; j++)
                acc2[i][j] = fmaf(ar[i], vr[j], acc2[i][j]);
    }
#pragma unroll
    for (int i = 0; i < 8; i++) {
        const int t = ty * 8 + i;
        *(float4*)(g_att + base + (size_t)t * 128 + tx * 8)     = make_float4(acc2[i][0], acc2[i][1], acc2[i][2], acc2[i][3]);
        *(float4*)(g_att + base + (size_t)t * 128 + tx * 8 + 4) = make_float4(acc2[i][4], acc2[i][5], acc2[i][6], acc2[i][7]);
    }
    __syncthreads();

    for (int idx = tid * 4; idx < Cn * Mn; idx += 1024)
        *(float4*)(B1 + idx) = *(const float4*)(g_k + base + idx);
    __syncthreads();

    float acc3[8][8];
#pragma unroll
    for (int i = 0; i < 8; i++)
#pragma unroll
        for (int j = 0; j < 8; j++) acc3[i][j] = 0.f;
    for (int u = 0; u < 128; u++) {
        const float w = LRF * dpow[127 - u];
        float vr[8], kr[8];
        LOAD8(vr, &B2[u * 128 + ty * 8]);
        LOAD8(kr, &B1[u * 128 + tx * 8]);
        float vw[8];
#pragma unroll
        for (int i = 0; i < 8; i++) vw[i] = vr[i] * w;
#pragma unroll
        for (int i = 0; i < 8; i++)
#pragma unroll
            for (int j = 0; j < 8; j++)
                acc3[i][j] = fmaf(vw[i], kr[j], acc3[i][j]);
    }
    const size_t dsbase = ((size_t)b * NCn + c) * (Mn * Mn);
#pragma unroll
    for (int i = 0; i < 8; i++) {
        const int r = ty * 8 + i;
        *(float4*)(g_dS + dsbase + (size_t)r * 128 + tx * 8)     = make_float4(acc3[i][0], acc3[i][1], acc3[i][2], acc3[i][3]);
        *(float4*)(g_dS + dsbase + (size_t)r * 128 + tx * 8 + 4) = make_float4(acc3[i][4], acc3[i][5], acc3[i][6], acc3[i][7]);
    }
}

// ===========================================================================
// K3: prefix over chunks
// ===========================================================================
__global__ void __launch_bounds__(256) scan_kernel(float* __restrict__ state_out)
{
    const int g  = blockIdx.x * blockDim.x + threadIdx.x;
    const int b  = g >> 14;
    const int ij = g & 16383;
    const float dc = powf(DECAYF, (float)Cn);
    float s = 0.f;
    for (int c = 0; c < NCn; c++) {
        const size_t idx = ((size_t)b * NCn + c) * 16384 + ij;
        g_S[idx] = s;
        s = dc * s + g_dS[idx];
    }
    state_out[g] = s;
}

// ===========================================================================
extern "C" void kernel_launch(void* const* d_in, const int* in_sizes, int n_in,
                              void* d_out, int out_size)
{
    const float* x  = (const float*)d_in[0];
    const float* Wk = (const float*)d_in[1];
    const float* bk = (const float*)d_in[2];
    const float* Wv = (const float*)d_in[3];
    const float* bv = (const float*)d_in[4];
    const float* Wq = (const float*)d_in[5];
    const float* bq = (const float*)d_in[6];
    const float* Wo = (const float*)d_in[7];
    const float* bo = (const float*)d_in[8];

    float* y         = (float*)d_out;
    float* state_out = y + (size_t)BSn * Dn;

    cudaFuncSetAttribute(chunk_kernel, cudaFuncAttributeMaxDynamicSharedMemorySize, 197120);

    proj_mma_kernel<<<dim3(BSn / 128, 3), 256>>>(x, Wk, bk, Wv, bv, Wq, bq);
    chunk_kernel<<<Bn * NCn, 256, 197120>>>();
    scan_kernel<<<(Bn * Mn * Mn) / 256, 256>>>(state_out);
    inter_mma_kernel<<<Bn * NCn, 256>>>();
    outproj_mma_kernel<<<dim3(BSn / 128, Dn / 128), 256>>>(Wo, bo, y);
}

// round 5
// speedup vs baseline: 2.9819x; 2.0102x over previous
#include <cuda_runtime.h>
#include <math.h>
#include <stdint.h>

// Problem constants
#define Bn   4
#define Sn   4096
#define Dn   1024
#define Mn   128
#define Cn   128
#define NCn  (Sn / Cn)
#define BSn  (Bn * Sn)
#define DECAYF 0.99f
#define LRF    0.01f

// Scratch (device globals)
__device__ float g_k  [BSn * Mn];
__device__ float g_v  [BSn * Mn];
__device__ float g_q  [BSn * Mn];
__device__ float g_att[BSn * Mn];
__device__ float g_dS [Bn * NCn * Mn * Mn];
__device__ float g_S  [Bn * NCn * Mn * Mn];

// ===========================================================================
// helpers
// ===========================================================================
__device__ __forceinline__ uint32_t smem_u32(const void* p) {
    uint32_t a;
    asm("{ .reg .u64 t; cvta.to.shared.u64 t, %1; cvt.u32.u64 %0, t; }"
        : "=r"(a) : "l"(p));
    return a;
}
__device__ __forceinline__ float to_tf32(float x) {
    float y;
    asm("cvt.rna.tf32.f32 %0, %1;" : "=f"(y) : "f"(x));
    return y;
}
__device__ __forceinline__ void mma_16n8k8(float* d, const uint32_t* a, const uint32_t* b) {
    asm volatile(
        "mma.sync.aligned.m16n8k8.row.col.f32.tf32.tf32.f32 "
        "{%0,%1,%2,%3}, {%4,%5,%6,%7}, {%8,%9}, {%0,%1,%2,%3};"
        : "+f"(d[0]), "+f"(d[1]), "+f"(d[2]), "+f"(d[3])
        : "r"(a[0]), "r"(a[1]), "r"(a[2]), "r"(a[3]), "r"(b[0]), "r"(b[1]));
}
#define CPASYNC16(sa, gp) \
    asm volatile("cp.async.ca.shared.global [%0], [%1], 16;" :: "r"(sa), "l"(gp))
#define CPCOMMIT() asm volatile("cp.async.commit_group;")
#define CPWAIT2()  asm volatile("cp.async.wait_group 2;")

extern __shared__ float sm_dyn[];

// ===========================================================================
// Shared tf32 GEMM, cp.async 4-stage pipeline.
// C[128,128] = A[128,K] * Bm^T (+bias / +=rowscale), 256 threads, 8 warps 4x2,
// warp tile 32x64. K-chunk 16, smem stage = 128x20 floats per operand.
// Dynamic smem: 4*2560*2 floats = 81920 B.
// ===========================================================================
#define SMLD 20
#define STGF 2560            // floats per operand stage

template<bool ACCUM, bool ROWSCALE>
__device__ __forceinline__ void gemm_v2(
    const float* __restrict__ A, int lda,
    const float* __restrict__ Bm, int ldb, int K,
    const float* __restrict__ bias,
    float* __restrict__ C, int ldc)
{
    float* sA = sm_dyn;
    float* sB = sm_dyn + 4 * STGF;
    const uint32_t sAu = smem_u32(sA);
    const uint32_t sBu = smem_u32(sB);
    const int tid = threadIdx.x;
    const int lane = tid & 31, wid = tid >> 5;
    const int wm = wid >> 1, wn = wid & 1;
    const int g = lane >> 2, t4 = lane & 3;

    // staging segments
    const int row0 = tid >> 2,          c40 = (tid & 3) * 4;
    const int row1 = (tid + 256) >> 2,  c41 = c40;    // seg1 = tid+256 -> same c4

    float acc[2][8][4];
#pragma unroll
    for (int mt = 0; mt < 2; mt++)
#pragma unroll
        for (int nt = 0; nt < 8; nt++)
#pragma unroll
            for (int r = 0; r < 4; r++) acc[mt][nt][r] = 0.f;

    const int nc = K >> 4;

#define ISSUE(ch) do { \
    const int _buf = (ch) & 3; \
    const int _k0 = (ch) * 16; \
    CPASYNC16(sAu + (_buf * STGF + row0 * SMLD + c40) * 4, A  + (size_t)row0 * lda + _k0 + c40); \
    CPASYNC16(sBu + (_buf * STGF + row0 * SMLD + c40) * 4, Bm + (size_t)row0 * ldb + _k0 + c40); \
    CPASYNC16(sAu + (_buf * STGF + row1 * SMLD + c41) * 4, A  + (size_t)row1 * lda + _k0 + c41); \
    CPASYNC16(sBu + (_buf * STGF + row1 * SMLD + c41) * 4, Bm + (size_t)row1 * ldb + _k0 + c41); \
} while (0)

    ISSUE(0); CPCOMMIT();
    ISSUE(1); CPCOMMIT();
    ISSUE(2); CPCOMMIT();

    for (int ch = 0; ch < nc; ch++) {
        CPWAIT2();
        __syncthreads();
        if (ch + 3 < nc) ISSUE(ch + 3);
        CPCOMMIT();

        const float* pa = sA + (ch & 3) * STGF;
        const float* pb = sB + (ch & 3) * STGF;
#pragma unroll
        for (int ks = 0; ks < 2; ks++) {
            const int ko = ks * 8;
            uint32_t af[2][4];
#pragma unroll
            for (int mt = 0; mt < 2; mt++) {
                const int br = wm * 32 + mt * 16;
                af[mt][0] = __float_as_uint(to_tf32(pa[(br + g    ) * SMLD + ko + t4    ]));
                af[mt][1] = __float_as_uint(to_tf32(pa[(br + g + 8) * SMLD + ko + t4    ]));
                af[mt][2] = __float_as_uint(to_tf32(pa[(br + g    ) * SMLD + ko + t4 + 4]));
                af[mt][3] = __float_as_uint(to_tf32(pa[(br + g + 8) * SMLD + ko + t4 + 4]));
            }
#pragma unroll
            for (int nt = 0; nt < 8; nt++) {
                const int bn = wn * 64 + nt * 8 + g;
                uint32_t bf[2];
                bf[0] = __float_as_uint(to_tf32(pb[bn * SMLD + ko + t4    ]));
                bf[1] = __float_as_uint(to_tf32(pb[bn * SMLD + ko + t4 + 4]));
                mma_16n8k8(acc[0][nt], af[0], bf);
                mma_16n8k8(acc[1][nt], af[1], bf);
            }
        }
    }
#undef ISSUE

    // epilogue
#pragma unroll
    for (int mt = 0; mt < 2; mt++) {
        const int r0 = wm * 32 + mt * 16 + g;
#pragma unroll
        for (int nt = 0; nt < 8; nt++) {
            const int c0 = wn * 64 + nt * 8 + 2 * t4;
            float* p0 = C + (size_t)r0 * ldc + c0;
            float* p1 = C + (size_t)(r0 + 8) * ldc + c0;
            if (ACCUM) {
                float s0 = 1.f, s1 = 1.f;
                if (ROWSCALE) { s0 = powf(DECAYF, (float)r0); s1 = powf(DECAYF, (float)(r0 + 8)); }
                float2 o0 = *(float2*)p0, o1 = *(float2*)p1;
                o0.x += s0 * acc[mt][nt][0]; o0.y += s0 * acc[mt][nt][1];
                o1.x += s1 * acc[mt][nt][2]; o1.y += s1 * acc[mt][nt][3];
                *(float2*)p0 = o0; *(float2*)p1 = o1;
            } else {
                float b0 = bias ? bias[c0] : 0.f;
                float b1 = bias ? bias[c0 + 1] : 0.f;
                float2 o0, o1;
                o0.x = acc[mt][nt][0] + b0; o0.y = acc[mt][nt][1] + b1;
                o1.x = acc[mt][nt][2] + b0; o1.y = acc[mt][nt][3] + b1;
                *(float2*)p0 = o0; *(float2*)p1 = o1;
            }
        }
    }
}

// ===========================================================================
// K1: projections   grid (128, 3)
// ===========================================================================
__global__ void __launch_bounds__(256) proj_mma_kernel(
    const float* __restrict__ x,
    const float* __restrict__ Wk, const float* __restrict__ bk,
    const float* __restrict__ Wv, const float* __restrict__ bv,
    const float* __restrict__ Wq, const float* __restrict__ bq)
{
    const size_t rb = (size_t)blockIdx.x * 128;
    const float* W; const float* bias; float* outp;
    if (blockIdx.y == 0)      { W = Wk; bias = bk; outp = g_k; }
    else if (blockIdx.y == 1) { W = Wv; bias = bv; outp = g_v; }
    else                      { W = Wq; bias = bq; outp = g_q; }
    gemm_v2<false, false>(x + rb * Dn, Dn, W, Dn, Dn, bias, outp + rb * Mn, Mn);
}

// ===========================================================================
// K5: y = att @ Wo^T + bo   grid (128, 8)
// ===========================================================================
__global__ void __launch_bounds__(256) outproj_mma_kernel(
    const float* __restrict__ Wo, const float* __restrict__ bo, float* __restrict__ y)
{
    const size_t rb = (size_t)blockIdx.x * 128;
    const int    cb = blockIdx.y * 128;
    gemm_v2<false, false>(g_att + rb * Mn, Mn, Wo + (size_t)cb * Mn, Mn, Mn,
                          bo + cb, y + rb * Dn + cb, Dn);
}

// ===========================================================================
// K4: out[t][i] += decay^t * sum_j S_c[i][j]*q_t[j]   grid (128)
// ===========================================================================
__global__ void __launch_bounds__(256) inter_mma_kernel()
{
    const int b = blockIdx.x / NCn;
    const int c = blockIdx.x % NCn;
    const size_t base  = ((size_t)b * Sn + (size_t)c * Cn) * Mn;
    const size_t sbase = ((size_t)b * NCn + c) * 16384;
    gemm_v2<true, true>(g_q + base, Mn, g_S + sbase, Mn, Mn,
                        (const float*)nullptr, g_att + base, Mn);
}

// ===========================================================================
// K2 (tensor, 3xTF32 compensated): per (b,c)
//   GEMM1: S[t][u] = q_t . k_u  -> mask u<t, * lr*decay^(t-1-u)
//   GEMM2: out[t][i] = sum_u S[t][u] V[u][i]
//   GEMM3: dS[i][j]  = sum_u (lr*decay^(127-u)) V[u][i] K[u][j]
// 256 threads, 8 warps 4x2, warp tile 32x64. Dyn smem 2*128*132*4 + 1024 B.
// ===========================================================================
#define SP 132

// 3xTF32: d += a*b with hi/lo split on both operands (drop lo*lo)
__device__ __forceinline__ void split4(const float* v, uint32_t* hi, uint32_t* lo) {
#pragma unroll
    for (int i = 0; i < 4; i++) {
        float h = to_tf32(v[i]);
        hi[i] = __float_as_uint(h);
        lo[i] = __float_as_uint(to_tf32(v[i] - h));
    }
}
__device__ __forceinline__ void split2(const float* v, uint32_t* hi, uint32_t* lo) {
#pragma unroll
    for (int i = 0; i < 2; i++) {
        float h = to_tf32(v[i]);
        hi[i] = __float_as_uint(h);
        lo[i] = __float_as_uint(to_tf32(v[i] - h));
    }
}

// acc[2][8][4] += Am(rows from wm band) x Bm(rows=cols), both [128][SP] fp32 in smem
__device__ __forceinline__ void gemm3x_128(const float* __restrict__ Am,
                                           const float* __restrict__ Bmm,
                                           float acc[2][8][4],
                                           int wm, int wn, int g, int t4)
{
#pragma unroll 4
    for (int ks = 0; ks < 16; ks++) {
        const int ko = ks * 8;
        uint32_t ah[2][4], al[2][4];
#pragma unroll
        for (int mt = 0; mt < 2; mt++) {
            const int br = wm * 32 + mt * 16;
            float av[4];
            av[0] = Am[(br + g    ) * SP + ko + t4    ];
            av[1] = Am[(br + g + 8) * SP + ko + t4    ];
            av[2] = Am[(br + g    ) * SP + ko + t4 + 4];
            av[3] = Am[(br + g + 8) * SP + ko + t4 + 4];
            split4(av, ah[mt], al[mt]);
        }
#pragma unroll
        for (int nt = 0; nt < 8; nt++) {
            const int bn = wn * 64 + nt * 8 + g;
            float bv[2];
            bv[0] = Bmm[bn * SP + ko + t4    ];
            bv[1] = Bmm[bn * SP + ko + t4 + 4];
            uint32_t bh[2], bl[2];
            split2(bv, bh, bl);
#pragma unroll
            for (int mt = 0; mt < 2; mt++) {
                mma_16n8k8(acc[mt][nt], ah[mt], bh);
                mma_16n8k8(acc[mt][nt], al[mt], bh);
                mma_16n8k8(acc[mt][nt], ah[mt], bl);
            }
        }
    }
}

__global__ void __launch_bounds__(256) chunk_mma_kernel()
{
    float* B0   = sm_dyn;              // K natural -> V^T
    float* B1   = B0 + 128 * SP;       // Q natural -> S -> Ktw
    float* dpow = B1 + 128 * SP;       // decay^0..127

    const int tid = threadIdx.x;
    const int lane = tid & 31, wid = tid >> 5;
    const int wm = wid >> 1, wn = wid & 1;
    const int g = lane >> 2, t4 = lane & 3;
    const int b = blockIdx.x / NCn;
    const int c = blockIdx.x % NCn;
    const size_t base = ((size_t)b * Sn + (size_t)c * Cn) * Mn;

    // load K -> B0, Q -> B1 (natural [row][d])
#pragma unroll
    for (int it = 0; it < 16; it++) {
        const int idx = (tid + it * 256) * 4;
        const int r = idx >> 7, d = idx & 127;
        *(float4*)(B0 + r * SP + d) = *(const float4*)(g_k + base + idx);
        *(float4*)(B1 + r * SP + d) = *(const float4*)(g_q + base + idx);
    }
    if (tid < 128) dpow[tid] = powf(DECAYF, (float)tid);
    __syncthreads();

    // GEMM1: S[t][u], A=Q(B1), B=K(B0)
    float acc[2][8][4];
#pragma unroll
    for (int mt = 0; mt < 2; mt++)
#pragma unroll
        for (int nt = 0; nt < 8; nt++)
#pragma unroll
            for (int r = 0; r < 4; r++) acc[mt][nt][r] = 0.f;
    gemm3x_128(B1, B0, acc, wm, wn, g, t4);

    // mask + decay factor
#pragma unroll
    for (int mt = 0; mt < 2; mt++)
#pragma unroll
        for (int nt = 0; nt < 8; nt++)
#pragma unroll
            for (int r = 0; r < 4; r++) {
                const int t = wm * 32 + mt * 16 + g + ((r >= 2) ? 8 : 0);
                const int u = wn * 64 + nt * 8 + 2 * t4 + (r & 1);
                acc[mt][nt][r] = (u < t) ? acc[mt][nt][r] * (LRF * dpow[t - 1 - u]) : 0.f;
            }
    __syncthreads();

    // store S -> B1 ; load V^T -> B0
#pragma unroll
    for (int mt = 0; mt < 2; mt++) {
        const int r0 = wm * 32 + mt * 16 + g;
#pragma unroll
        for (int nt = 0; nt < 8; nt++) {
            const int c0 = wn * 64 + nt * 8 + 2 * t4;
            *(float2*)(B1 + r0 * SP + c0)       = make_float2(acc[mt][nt][0], acc[mt][nt][1]);
            *(float2*)(B1 + (r0 + 8) * SP + c0) = make_float2(acc[mt][nt][2], acc[mt][nt][3]);
        }
    }
#pragma unroll
    for (int it = 0; it < 16; it++) {
        const int idx = (tid + it * 256) * 4;
        const int u = idx >> 7, i0 = idx & 127;
        float4 v = *(const float4*)(g_v + base + idx);
        B0[(i0 + 0) * SP + u] = v.x;
        B0[(i0 + 1) * SP + u] = v.y;
        B0[(i0 + 2) * SP + u] = v.z;
        B0[(i0 + 3) * SP + u] = v.w;
    }
    __syncthreads();

    // GEMM2: out[t][i] = S(B1) x V^T(B0)
    float acc2[2][8][4];
#pragma unroll
    for (int mt = 0; mt < 2; mt++)
#pragma unroll
        for (int nt = 0; nt < 8; nt++)
#pragma unroll
            for (int r = 0; r < 4; r++) acc2[mt][nt][r] = 0.f;
    gemm3x_128(B1, B0, acc2, wm, wn, g, t4);
#pragma unroll
    for (int mt = 0; mt < 2; mt++) {
        const int r0 = wm * 32 + mt * 16 + g;
#pragma unroll
        for (int nt = 0; nt < 8; nt++) {
            const int c0 = wn * 64 + nt * 8 + 2 * t4;
            *(float2*)(g_att + base + (size_t)r0 * Mn + c0)       = make_float2(acc2[mt][nt][0], acc2[mt][nt][1]);
            *(float2*)(g_att + base + (size_t)(r0 + 8) * Mn + c0) = make_float2(acc2[mt][nt][2], acc2[mt][nt][3]);
        }
    }
    __syncthreads();

    // load Ktw -> B1:  Ktw[j][u] = K[u][j] * lr*decay^(127-u)
#pragma unroll
    for (int it = 0; it < 16; it++) {
        const int idx = (tid + it * 256) * 4;
        const int u = idx >> 7, j0 = idx & 127;
        const float w = LRF * dpow[127 - u];
        float4 k = *(const float4*)(g_k + base + idx);
        B1[(j0 + 0) * SP + u] = k.x * w;
        B1[(j0 + 1) * SP + u] = k.y * w;
        B1[(j0 + 2) * SP + u] = k.z * w;
        B1[(j0 + 3) * SP + u] = k.w * w;
    }
    __syncthreads();

    // GEMM3: dS[i][j] = V^T(B0) x Ktw(B1)
    float acc3[2][8][4];
#pragma unroll
    for (int mt = 0; mt < 2; mt++)
#pragma unroll
        for (int nt = 0; nt < 8; nt++)
#pragma unroll
            for (int r = 0; r < 4; r++) acc3[mt][nt][r] = 0.f;
    gemm3x_128(B0, B1, acc3, wm, wn, g, t4);

    const size_t dsbase = ((size_t)b * NCn + c) * (Mn * Mn);
#pragma unroll
    for (int mt = 0; mt < 2; mt++) {
        const int r0 = wm * 32 + mt * 16 + g;
#pragma unroll
        for (int nt = 0; nt < 8; nt++) {
            const int c0 = wn * 64 + nt * 8 + 2 * t4;
            *(float2*)(g_dS + dsbase + (size_t)r0 * Mn + c0)       = make_float2(acc3[mt][nt][0], acc3[mt][nt][1]);
            *(float2*)(g_dS + dsbase + (size_t)(r0 + 8) * Mn + c0) = make_float2(acc3[mt][nt][2], acc3[mt][nt][3]);
        }
    }
}

// ===========================================================================
// K3: prefix over chunks
// ===========================================================================
__global__ void __launch_bounds__(256) scan_kernel(float* __restrict__ state_out)
{
    const int g  = blockIdx.x * blockDim.x + threadIdx.x;
    const int b  = g >> 14;
    const int ij = g & 16383;
    const float dc = powf(DECAYF, (float)Cn);
    float s = 0.f;
    for (int c = 0; c < NCn; c++) {
        const size_t idx = ((size_t)b * NCn + c) * 16384 + ij;
        g_S[idx] = s;
        s = dc * s + g_dS[idx];
    }
    state_out[g] = s;
}

// ===========================================================================
extern "C" void kernel_launch(void* const* d_in, const int* in_sizes, int n_in,
                              void* d_out, int out_size)
{
    const float* x  = (const float*)d_in[0];
    const float* Wk = (const float*)d_in[1];
    const float* bk = (const float*)d_in[2];
    const float* Wv = (const float*)d_in[3];
    const float* bv = (const float*)d_in[4];
    const float* Wq = (const float*)d_in[5];
    const float* bq = (const float*)d_in[6];
    const float* Wo = (const float*)d_in[7];
    const float* bo = (const float*)d_in[8];

    float* y         = (float*)d_out;
    float* state_out = y + (size_t)BSn * Dn;

    const int GEMM_SMEM  = 4 * STGF * 2 * 4;                 // 81920
    const int CHUNK_SMEM = (2 * 128 * SP + 128) * 4 + 512;   // ~135.9KB

    cudaFuncSetAttribute(proj_mma_kernel,    cudaFuncAttributeMaxDynamicSharedMemorySize, GEMM_SMEM);
    cudaFuncSetAttribute(outproj_mma_kernel, cudaFuncAttributeMaxDynamicSharedMemorySize, GEMM_SMEM);
    cudaFuncSetAttribute(inter_mma_kernel,   cudaFuncAttributeMaxDynamicSharedMemorySize, GEMM_SMEM);
    cudaFuncSetAttribute(chunk_mma_kernel,   cudaFuncAttributeMaxDynamicSharedMemorySize, CHUNK_SMEM);

    proj_mma_kernel<<<dim3(BSn / 128, 3), 256, GEMM_SMEM>>>(x, Wk, bk, Wv, bv, Wq, bq);
    chunk_mma_kernel<<<Bn * NCn, 256, CHUNK_SMEM>>>();
    scan_kernel<<<(Bn * Mn * Mn) / 256, 256>>>(state_out);
    inter_mma_kernel<<<Bn * NCn, 256, GEMM_SMEM>>>();
    outproj_mma_kernel<<<dim3(BSn / 128, Dn / 128), 256, GEMM_SMEM>>>(Wo, bo, y);
}